// round 11
// baseline (speedup 1.0000x reference)
#include <cuda_runtime.h>
#include <cuda_fp16.h>
#include <cstdint>
#include <cstring>

// Fused MoE, fp16 ldmatrix+mma.m16n8k16 edition.
#define T_TOKENS 1024
#define DIM   1024
#define INTER 512
#define NEXP  16
#define TOPK  4
#define NROWS 5120
#define TMF   64
#define MAXT  96
#define STB   80        // fp16 stage row stride bytes (32 halves + pad)
#define HSB   1040      // Hs row stride bytes (520 halves)
#define HSW   260       // Hs row stride in u32 words
#define P1G   5120      // gate array offset in phase-1 stage
#define P1U   10240     // up array offset
#define P1S   15360     // phase-1 stage size
#define P2S   10240     // phase-2 stage size

struct TileDesc { int e; int row0; int rows; };

__device__ int      g_counts[NEXP];
__device__ int      g_off[NEXP + 1];
__device__ int      g_idx[T_TOKENS * TOPK];
__device__ float    g_w[T_TOKENS * TOPK];
__device__ int      g_row_token[NROWS];
__device__ float    g_row_weight[NROWS];
__device__ TileDesc g_tiles[MAXT];
__device__ int      g_ntiles;

#define SM_HS    0          // 64 x 1040 = 66560
#define SM_ST    66560      // 2 stages (ph1 15360 / ph2 10240 each)
#define SM_RTOK  97280
#define SM_RWT   97536
#define SM_TOTAL 97792

__global__ void init_kernel() {
    if (threadIdx.x < NEXP) g_counts[threadIdx.x] = 0;
}

__global__ __launch_bounds__(256)
void gate_kernel(const float* __restrict__ x, const float* __restrict__ gw,
                 const float* __restrict__ gb) {
    const int token = (blockIdx.x * blockDim.x + threadIdx.x) >> 5;
    const int lane  = threadIdx.x & 31;
    if (token >= T_TOKENS) return;
    const float* xt = x + (size_t)token * DIM;
    float myscore = 0.f;
    for (int e = 0; e < NEXP; e++) {
        const float* we = gw + e * DIM;
        float p = 0.f;
        #pragma unroll 4
        for (int d = lane; d < DIM; d += 32) p += xt[d] * we[d];
        #pragma unroll
        for (int o = 16; o; o >>= 1) p += __shfl_xor_sync(0xffffffffu, p, o);
        if (lane == e) myscore = 1.0f / (1.0f + expf(-p));
    }
    float mybiased = (lane < NEXP) ? (myscore + gb[lane]) : -1e30f;
    float sum = 0.f; int kidx[TOPK]; float kw[TOPK];
    #pragma unroll
    for (int k = 0; k < TOPK; k++) {
        float v = mybiased; int bl = lane;
        #pragma unroll
        for (int o = 16; o; o >>= 1) {
            float ov = __shfl_xor_sync(0xffffffffu, v, o);
            int   ol = __shfl_xor_sync(0xffffffffu, bl, o);
            if (ov > v || (ov == v && ol < bl)) { v = ov; bl = ol; }
        }
        float sc = __shfl_sync(0xffffffffu, myscore, bl);
        kidx[k] = bl; kw[k] = sc; sum += sc;
        if (lane == bl) mybiased = -1e30f;
    }
    const float s = 2.5f / sum;
    if (lane == 0) {
        #pragma unroll
        for (int k = 0; k < TOPK; k++) {
            g_idx[token * TOPK + k] = kidx[k];
            g_w[token * TOPK + k]   = kw[k] * s;
            atomicAdd(&g_counts[kidx[k]], 1);
        }
        g_row_token[4096 + token]  = token;
        g_row_weight[4096 + token] = 1.0f;
    }
}

__global__ void sched_kernel() {
    int off = 0, nt = 0;
    for (int e = 0; e < NEXP; e++) {
        g_off[e] = off;
        int c = g_counts[e];
        for (int i = 0; i < c; i += TMF) {
            g_tiles[nt].e = e; g_tiles[nt].row0 = off + i;
            g_tiles[nt].rows = min(TMF, c - i); nt++;
        }
        off += c;
    }
    g_off[NEXP] = off;
    for (int i = 0; i < T_TOKENS; i += TMF) {
        g_tiles[nt].e = NEXP; g_tiles[nt].row0 = 4096 + i; g_tiles[nt].rows = TMF;
        nt++;
    }
    g_ntiles = nt;
}

__global__ void place_kernel() {
    __shared__ int s[T_TOKENS];
    int e = blockIdx.x, t = threadIdx.x;
    int myk = -1;
    #pragma unroll
    for (int k = 0; k < TOPK; k++)
        if (g_idx[t * TOPK + k] == e) myk = k;
    s[t] = (myk >= 0) ? 1 : 0;
    __syncthreads();
    for (int off = 1; off < T_TOKENS; off <<= 1) {
        int v = (t >= off) ? s[t - off] : 0;
        __syncthreads();
        s[t] += v;
        __syncthreads();
    }
    if (myk >= 0) {
        int row = g_off[e] + s[t] - 1;
        g_row_token[row]  = t;
        g_row_weight[row] = g_w[t * TOPK + myk];
    }
}

__device__ __forceinline__ uint32_t pk(float a, float b) {
    uint32_t r;
    asm("cvt.rn.f16x2.f32 %0, %1, %2;" : "=r"(r) : "f"(b), "f"(a));
    return r;   // lo=a hi=b
}
__device__ __forceinline__ void mma16(float* d, const uint32_t* a, const uint32_t* b) {
    asm volatile(
        "mma.sync.aligned.m16n8k16.row.col.f32.f16.f16.f32 "
        "{%0,%1,%2,%3},{%4,%5,%6,%7},{%8,%9},{%0,%1,%2,%3};"
        : "+f"(d[0]), "+f"(d[1]), "+f"(d[2]), "+f"(d[3])
        : "r"(a[0]), "r"(a[1]), "r"(a[2]), "r"(a[3]), "r"(b[0]), "r"(b[1]));
}
__device__ __forceinline__ void lx4(uint32_t* r, uint32_t a) {
    asm volatile("ldmatrix.sync.aligned.m8n8.x4.shared.b16 {%0,%1,%2,%3}, [%4];"
        : "=r"(r[0]), "=r"(r[1]), "=r"(r[2]), "=r"(r[3]) : "r"(a));
}
__device__ __forceinline__ void lx2(uint32_t* r, uint32_t a) {
    asm volatile("ldmatrix.sync.aligned.m8n8.x2.shared.b16 {%0,%1}, [%2];"
        : "=r"(r[0]), "=r"(r[1]) : "r"(a));
}
__device__ __forceinline__ void st128(uint32_t a, uint32_t q0, uint32_t q1,
                                      uint32_t q2, uint32_t q3) {
    asm volatile("st.shared.v4.b32 [%0], {%1,%2,%3,%4};"
        :: "r"(a), "r"(q0), "r"(q1), "r"(q2), "r"(q3) : "memory");
}

__global__ __launch_bounds__(256, 1)
void fused_kernel(const float* __restrict__ x, const float* __restrict__ w13,
                  const float* __restrict__ w2, const float* __restrict__ w13_s,
                  const float* __restrict__ w2_s, float* __restrict__ out) {
    const int tile = blockIdx.x;
    if (tile >= g_ntiles) return;
    const TileDesc td = g_tiles[tile];
    const int row0 = td.row0, rows = td.rows;
    const float* B1 = (td.e < NEXP) ? (w13 + (size_t)td.e * 1024 * DIM) : w13_s;
    const float* B2 = (td.e < NEXP) ? (w2  + (size_t)td.e * DIM * INTER) : w2_s;

    extern __shared__ char smem[];
    uint32_t* Hs32 = (uint32_t*)smem;
    int*      rtok = (int*)(smem + SM_RTOK);
    float*    rwt  = (float*)(smem + SM_RWT);
    const uint32_t smA = (uint32_t)__cvta_generic_to_shared(smem);
    const uint32_t hsA = smA, stA = smA + SM_ST;

    const int tid = threadIdx.x, lane = tid & 31, warp = tid >> 5;
    const int wm = warp >> 2, wn = warp & 3;       // 2m x 4n
    const int g  = lane >> 2, tg = lane & 3;

    if (tid < TMF) {
        bool v = tid < rows;
        rtok[tid] = v ? g_row_token[row0 + tid] : 0;
        rwt[tid]  = v ? g_row_weight[row0 + tid] : 0.f;
    }
    __syncthreads();

    // ldmatrix lane addresses (stage / Hs)
    const uint32_t aLd  = stA + (wm * 32 + (lane & 15)) * STB + (lane >> 4) * 16;
    const uint32_t bLd  = stA + P1G + (wn * 16 + (lane & 7)) * STB + ((lane >> 3) & 1) * 16;
    const uint32_t hLd  = hsA + (wm * 32 + (lane & 15)) * HSB + (lane >> 4) * 16;
    const uint32_t b2Ld = stA + (wn * 32 + (lane & 7)) * STB + ((lane >> 3) & 1) * 16;

    // ================= Phase 1: h = silu(x@Wg^T)*(x@Wu^T) -> Hs =============
    {
        const int r1 = tid & 63, s1 = tid >> 6;          // seg 0..3 (8 floats)
        const float* aS = x + (size_t)rtok[r1] * DIM + s1 * 8;
        const float* gS = B1 + (size_t)r1 * DIM + s1 * 8;
        const float* uS = gS + (size_t)512 * DIM;
        const uint32_t p1d = stA + r1 * STB + s1 * 16;
        float4 va[2], vg[2], vu[2];

#define LDG1(k, co) do { const int _o = (k) * 32;                               \
    va[0] = *(const float4*)(aS + _o);        va[1] = *(const float4*)(aS + _o + 4); \
    vg[0] = *(const float4*)(gS + (co) + _o); vg[1] = *(const float4*)(gS + (co) + _o + 4); \
    vu[0] = *(const float4*)(uS + (co) + _o); vu[1] = *(const float4*)(uS + (co) + _o + 4); } while (0)
#define STS1(b) do { const uint32_t _d = p1d + (b) * P1S;                       \
    st128(_d,       pk(va[0].x,va[0].y), pk(va[0].z,va[0].w), pk(va[1].x,va[1].y), pk(va[1].z,va[1].w)); \
    st128(_d + P1G, pk(vg[0].x,vg[0].y), pk(vg[0].z,vg[0].w), pk(vg[1].x,vg[1].y), pk(vg[1].z,vg[1].w)); \
    st128(_d + P1U, pk(vu[0].x,vu[0].y), pk(vu[0].z,vu[0].w), pk(vu[1].x,vu[1].y), pk(vu[1].z,vu[1].w)); } while (0)

        for (int nc = 0; nc < 8; nc++) {
            const size_t co = (size_t)nc * 64 * DIM;
            float accG[2][2][4], accU[2][2][4];
            #pragma unroll
            for (int mi = 0; mi < 2; mi++)
                #pragma unroll
                for (int ni = 0; ni < 2; ni++)
                    #pragma unroll
                    for (int q = 0; q < 4; q++) { accG[mi][ni][q] = 0.f; accU[mi][ni][q] = 0.f; }

            LDG1(0, co);
            __syncthreads();                 // prev chunk done with stages
            STS1(0);
            LDG1(1, co);
            __syncthreads();
            #pragma unroll 1
            for (int it = 0; it < 32; it++) {
                if (it + 1 < 32) { STS1((it + 1) & 1); if (it + 2 < 32) LDG1(it + 2, co); }
                const uint32_t bo = (uint32_t)(it & 1) * P1S;
                #pragma unroll
                for (int ks = 0; ks < 2; ks++) {
                    const uint32_t ko = bo + ks * 32;
                    uint32_t af[2][4], bg[2][2], bu[2][2];
                    lx4(af[0], aLd + ko); lx4(af[1], aLd + ko + 16 * STB);
                    lx2(bg[0], bLd + ko); lx2(bg[1], bLd + ko + 8 * STB);
                    lx2(bu[0], bLd + 5120 + ko); lx2(bu[1], bLd + 5120 + ko + 8 * STB);
                    #pragma unroll
                    for (int mi = 0; mi < 2; mi++)
                        #pragma unroll
                        for (int ni = 0; ni < 2; ni++) {
                            mma16(accG[mi][ni], af[mi], bg[ni]);
                            mma16(accU[mi][ni], af[mi], bu[ni]);
                        }
                }
                __syncthreads();
            }
            // epilogue -> Hs fp16
            #pragma unroll
            for (int mi = 0; mi < 2; mi++) {
                const int r0 = wm * 32 + mi * 16 + g, r1e = r0 + 8;
                #pragma unroll
                for (int ni = 0; ni < 2; ni++) {
                    const int c = nc * 64 + wn * 16 + ni * 8 + 2 * tg;
                    float g0 = accG[mi][ni][0], g1 = accG[mi][ni][1];
                    float h0 = (g0 / (1.0f + expf(-g0))) * accU[mi][ni][0];
                    float h1 = (g1 / (1.0f + expf(-g1))) * accU[mi][ni][1];
                    Hs32[r0 * HSW + (c >> 1)] = pk(h0, h1);
                    float g2 = accG[mi][ni][2], g3 = accG[mi][ni][3];
                    float h2 = (g2 / (1.0f + expf(-g2))) * accU[mi][ni][2];
                    float h3 = (g3 / (1.0f + expf(-g3))) * accU[mi][ni][3];
                    Hs32[r1e * HSW + (c >> 1)] = pk(h2, h3);
                }
            }
        }
    }

    // ================= Phase 2: y = (h @ W2^T) * w -> atomicAdd =============
    {
        const int r2 = tid & 127, s2 = tid >> 7;         // seg 0..1 (16 floats)
        const float* bS = B2 + (size_t)r2 * INTER + s2 * 16;
        const uint32_t p2d = stA + r2 * STB + s2 * 32;
        float4 vb[4];

#define LDG2(k, co) do { const float* _p = bS + (co) + (k) * 32;                \
    vb[0] = *(const float4*)_p;       vb[1] = *(const float4*)(_p + 4);         \
    vb[2] = *(const float4*)(_p + 8); vb[3] = *(const float4*)(_p + 12); } while (0)
#define STS2(b) do { const uint32_t _d = p2d + (b) * P2S;                       \
    st128(_d,      pk(vb[0].x,vb[0].y), pk(vb[0].z,vb[0].w), pk(vb[1].x,vb[1].y), pk(vb[1].z,vb[1].w)); \
    st128(_d + 16, pk(vb[2].x,vb[2].y), pk(vb[2].z,vb[2].w), pk(vb[3].x,vb[3].y), pk(vb[3].z,vb[3].w)); } while (0)

        for (int nb = 0; nb < 8; nb++) {
            const size_t co = (size_t)nb * 128 * INTER;
            float acc[2][4][4];
            #pragma unroll
            for (int mi = 0; mi < 2; mi++)
                #pragma unroll
                for (int ni = 0; ni < 4; ni++)
                    #pragma unroll
                    for (int q = 0; q < 4; q++) acc[mi][ni][q] = 0.f;

            LDG2(0, co);
            __syncthreads();                 // phase-1 stages free + Hs visible
            STS2(0);
            LDG2(1, co);
            __syncthreads();
            #pragma unroll 1
            for (int it = 0; it < 16; it++) {
                if (it + 1 < 16) { STS2((it + 1) & 1); if (it + 2 < 16) LDG2(it + 2, co); }
                const uint32_t bo = (uint32_t)(it & 1) * P2S;
                #pragma unroll
                for (int ks = 0; ks < 2; ks++) {
                    const uint32_t hko = (uint32_t)it * 64 + ks * 32;
                    uint32_t af[2][4], bf[4][2];
                    lx4(af[0], hLd + hko); lx4(af[1], hLd + hko + 16 * HSB);
                    #pragma unroll
                    for (int ni = 0; ni < 4; ni++)
                        lx2(bf[ni], b2Ld + bo + ni * 8 * STB + ks * 32);
                    #pragma unroll
                    for (int mi = 0; mi < 2; mi++)
                        #pragma unroll
                        for (int ni = 0; ni < 4; ni++)
                            mma16(acc[mi][ni], af[mi], bf[ni]);
                }
                __syncthreads();
            }
            // epilogue: weighted atomics
            #pragma unroll
            for (int mi = 0; mi < 2; mi++) {
                const int r0 = wm * 32 + mi * 16 + g, r1e = r0 + 8;
                const float w0 = rwt[r0], w1 = rwt[r1e];
                const int   t0 = rtok[r0], t1 = rtok[r1e];
                #pragma unroll
                for (int ni = 0; ni < 4; ni++) {
                    const int col = nb * 128 + wn * 32 + ni * 8 + 2 * tg;
                    float* q0 = out + (size_t)t0 * DIM + col;
                    float* q1 = out + (size_t)t1 * DIM + col;
                    atomicAdd(q0 + 0, acc[mi][ni][0] * w0);
                    atomicAdd(q0 + 1, acc[mi][ni][1] * w0);
                    atomicAdd(q1 + 0, acc[mi][ni][2] * w1);
                    atomicAdd(q1 + 1, acc[mi][ni][3] * w1);
                }
            }
        }
    }
}

namespace {
struct EagerInit {
    EagerInit() {
        cudaFuncAttributes a;
        (void)cudaFuncGetAttributes(&a, (const void*)init_kernel);
        (void)cudaFuncGetAttributes(&a, (const void*)gate_kernel);
        (void)cudaFuncGetAttributes(&a, (const void*)sched_kernel);
        (void)cudaFuncGetAttributes(&a, (const void*)place_kernel);
        (void)cudaFuncGetAttributes(&a, (const void*)fused_kernel);
        (void)cudaFuncSetAttribute((const void*)fused_kernel,
                                   cudaFuncAttributeMaxDynamicSharedMemorySize, SM_TOTAL);
        int zeros[NEXP];
        memset(zeros, 0, sizeof(zeros));
        (void)cudaMemcpyToSymbol(g_counts, zeros, sizeof(zeros));
        init_kernel<<<1, 32>>>();
        (void)cudaDeviceSynchronize();
        (void)cudaGetLastError();
    }
};
static EagerInit eager_init_instance;
}  // namespace

extern "C" void kernel_launch(void* const* d_in, const int* in_sizes, int n_in,
                              void* d_out, int out_size) {
    const float* x     = (const float*)d_in[0];
    const float* gw    = (const float*)d_in[2];
    const float* gb    = (const float*)d_in[3];
    const float* w13   = (const float*)d_in[4];
    const float* w2    = (const float*)d_in[5];
    const float* w13_s = (const float*)d_in[6];
    const float* w2_s  = (const float*)d_in[7];
    float* out = (float*)d_out;

    (void)cudaFuncSetAttribute((const void*)fused_kernel,
                               cudaFuncAttributeMaxDynamicSharedMemorySize, SM_TOTAL);

    cudaMemsetAsync(out, 0, (size_t)out_size * sizeof(float), 0);
    init_kernel<<<1, 32>>>();
    gate_kernel<<<T_TOKENS / 8, 256>>>(x, gw, gb);
    sched_kernel<<<1, 1>>>();
    place_kernel<<<NEXP, T_TOKENS>>>();
    fused_kernel<<<MAXT, 256, SM_TOTAL>>>(x, w13, w2, w13_s, w2_s, out);
}